// round 3
// baseline (speedup 1.0000x reference)
#include <cuda_runtime.h>
#include <cuda_bf16.h>

// Neural-ODE explicit Euler, 20 steps, fused persistent kernel.
// B=8192, LATENT=256, U=16, HIDDEN=512.
// Each CTA owns TM=32 batch rows; z lives in SMEM across all steps.
// Weights (W1: 272x512, W2: 512x256, fp32, ~1.08MB) are read from L2 every
// k-iteration; b1/b2 via L1.
//
// Layouts:
//   Zs: k-major [256][33] (pad 33 -> conflict-free update writes & transposed IO)
//   Hs: row-major [32][512] (reads are warp-broadcast; writes lane-consecutive)
//   Us: k-major [16][32]

#define NSTEPS   20
#define TM       32
#define LATENT   256
#define UDIM     16
#define HIDDEN   512
#define ZS_STRIDE 33
#define THREADS  256

__global__ __launch_bounds__(THREADS, 2)
void node_euler_kernel(const float* __restrict__ zt,
                       const float* __restrict__ dt,
                       const float* __restrict__ ut,
                       const float* __restrict__ W1,
                       const float* __restrict__ b1,
                       const float* __restrict__ W2,
                       const float* __restrict__ b2,
                       float* __restrict__ out)
{
    extern __shared__ float smem[];
    float* Zs    = smem;                               // [LATENT][ZS_STRIDE]
    float* Hs    = Zs + LATENT * ZS_STRIDE;            // [TM][HIDDEN]
    float* Us    = Hs + TM * HIDDEN;                   // [UDIM][TM]
    float* hstep = Us + UDIM * TM;                     // [TM]

    const int tid  = threadIdx.x;
    const int tx   = tid & 31;        // 0..31 (lane)
    const int ty   = tid >> 5;        // 0..7  (warp)
    const int row0 = blockIdx.x * TM;

    // ---- Load z tile (transposed into k-major Zs) ----
    for (int idx = tid; idx < TM * LATENT; idx += THREADS) {
        int r = idx >> 8;           // idx / 256
        int k = idx & 255;          // idx % 256
        Zs[k * ZS_STRIDE + r] = zt[(row0 + r) * LATENT + k];
    }
    // ---- Load u tile (k-major) ----
    for (int idx = tid; idx < TM * UDIM; idx += THREADS) {
        int r = idx >> 4;
        int k = idx & 15;
        Us[k * TM + r] = ut[(row0 + r) * UDIM + k];
    }
    // ---- Per-row step size h = dt/NSTEPS ----
    if (tid < TM) hstep[tid] = dt[row0 + tid] * (1.0f / NSTEPS);
    __syncthreads();

    const int rbase = ty * 4;   // this thread's 4 rows

    for (int s = 0; s < NSTEPS; s++) {
        // ================= GEMM1: H = tanh(X @ W1 + b1) =================
        // Thread tile: 4 rows x 16 cols (cols = tx + 32*j), 64 accumulators.
        float acc[16][4];
        #pragma unroll
        for (int j = 0; j < 16; j++) {
            float bv = b1[tx + 32 * j];
            #pragma unroll
            for (int r = 0; r < 4; r++) acc[j][r] = bv;
        }

        // K over latent part (z)
        #pragma unroll 2
        for (int k = 0; k < LATENT; k++) {
            float xr[4];
            #pragma unroll
            for (int r = 0; r < 4; r++)
                xr[r] = Zs[k * ZS_STRIDE + rbase + r];  // warp-broadcast
            const float* w = W1 + k * HIDDEN + tx;
            #pragma unroll
            for (int j = 0; j < 16; j++) {
                float wv = __ldg(w + 32 * j);            // 128B coalesced
                #pragma unroll
                for (int r = 0; r < 4; r++) acc[j][r] += wv * xr[r];
            }
        }
        // K over control part (u)
        #pragma unroll
        for (int k = 0; k < UDIM; k++) {
            float xr[4];
            #pragma unroll
            for (int r = 0; r < 4; r++)
                xr[r] = Us[k * TM + rbase + r];
            const float* w = W1 + (LATENT + k) * HIDDEN + tx;
            #pragma unroll
            for (int j = 0; j < 16; j++) {
                float wv = __ldg(w + 32 * j);
                #pragma unroll
                for (int r = 0; r < 4; r++) acc[j][r] += wv * xr[r];
            }
        }

        // tanh + store H (row-major; lanes write consecutive floats)
        #pragma unroll
        for (int j = 0; j < 16; j++) {
            #pragma unroll
            for (int r = 0; r < 4; r++) {
                Hs[(rbase + r) * HIDDEN + tx + 32 * j] = tanhf(acc[j][r]);
            }
        }
        __syncthreads();

        // ================= GEMM2: F = H @ W2 + b2;  z += h*F =================
        // Thread tile: 4 rows x 8 cols (cols = tx + 32*j), 32 accumulators.
        float acc2[8][4];
        #pragma unroll
        for (int j = 0; j < 8; j++) {
            float bv = b2[tx + 32 * j];
            #pragma unroll
            for (int r = 0; r < 4; r++) acc2[j][r] = bv;
        }

        #pragma unroll 2
        for (int k = 0; k < HIDDEN; k++) {
            float hr[4];
            #pragma unroll
            for (int r = 0; r < 4; r++)
                hr[r] = Hs[(rbase + r) * HIDDEN + k];    // warp-broadcast
            const float* w = W2 + k * LATENT + tx;
            #pragma unroll
            for (int j = 0; j < 8; j++) {
                float wv = __ldg(w + 32 * j);            // 128B coalesced
                #pragma unroll
                for (int r = 0; r < 4; r++) acc2[j][r] += wv * hr[r];
            }
        }

        // z update: Zs[col][row] += h[row] * F   (bank stride 33 -> conflict-free)
        #pragma unroll
        for (int j = 0; j < 8; j++) {
            int col = tx + 32 * j;
            #pragma unroll
            for (int r = 0; r < 4; r++) {
                int rr = rbase + r;
                Zs[col * ZS_STRIDE + rr] += hstep[rr] * acc2[j][r];
            }
        }
        __syncthreads();
    }

    // ---- Store z tile back (coalesced writes) ----
    for (int idx = tid; idx < TM * LATENT; idx += THREADS) {
        int r = idx >> 8;
        int k = idx & 255;
        out[(row0 + r) * LATENT + k] = Zs[k * ZS_STRIDE + r];
    }
}

extern "C" void kernel_launch(void* const* d_in, const int* in_sizes, int n_in,
                              void* d_out, int out_size)
{
    const float* zt = (const float*)d_in[0];
    const float* dt = (const float*)d_in[1];
    const float* ut = (const float*)d_in[2];
    const float* W1 = (const float*)d_in[3];
    const float* b1 = (const float*)d_in[4];
    const float* W2 = (const float*)d_in[5];
    const float* b2 = (const float*)d_in[6];
    float* out = (float*)d_out;

    const int B = 8192;
    const int grid = B / TM;   // 256 CTAs

    size_t smem_bytes = (size_t)(LATENT * ZS_STRIDE + TM * HIDDEN + UDIM * TM + TM) * sizeof(float);

    cudaFuncSetAttribute(node_euler_kernel,
                         cudaFuncAttributeMaxDynamicSharedMemorySize,
                         (int)smem_bytes);

    node_euler_kernel<<<grid, THREADS, smem_bytes>>>(zt, dt, ut, W1, b1, W2, b2, out);
}

// round 7
// speedup vs baseline: 1.3785x; 1.3785x over previous
#include <cuda_runtime.h>
#include <cuda_bf16.h>

// Neural-ODE explicit Euler, 20 fused steps, persistent CTA tile.
// B=8192, LATENT=256, U=16, HIDDEN=512.
// fp32x2 packed-FMA version: accumulators pack batch-row PAIRS into 64-bit
// regs driven by PTX fma.rn.f32x2 (FFMA2 — 2 fp32 MACs/issue on sm_103a).
//
// SMEM layouts (all k-major, row-PAIR packed, stride 17 pairs):
//   Zp: [LATENT][17]  float2-as-u64   (z state, persists across steps)
//   Hp: [HIDDEN][17]  float2-as-u64   (hidden activations)
//   Up: [UDIM][17]    float2-as-u64
//   hp: [16]          float2          (per-row-pair step size)

#define NSTEPS   20
#define TM       32
#define NP       16          // row pairs per CTA
#define LATENT   256
#define UDIM     16
#define HIDDEN   512
#define PSTRIDE  17          // pair stride (pad 1)
#define THREADS  256

typedef unsigned long long ull;

__device__ __forceinline__ ull pk2(float lo, float hi) {
    ull r; asm("mov.b64 %0, {%1, %2};" : "=l"(r) : "f"(lo), "f"(hi)); return r;
}
__device__ __forceinline__ float2 upk(ull v) {
    float2 r; asm("mov.b64 {%0, %1}, %2;" : "=f"(r.x), "=f"(r.y) : "l"(v)); return r;
}
// d = a * b + d on packed f32x2 (both lanes independent)
#define FFMA2(d, a, b) asm("fma.rn.f32x2 %0, %1, %2, %0;" : "+l"(d) : "l"(a), "l"(b))

__global__ __launch_bounds__(THREADS, 2)
void node_euler_f32x2(const float* __restrict__ zt,
                      const float* __restrict__ dt,
                      const float* __restrict__ ut,
                      const float* __restrict__ W1,
                      const float* __restrict__ b1,
                      const float* __restrict__ W2,
                      const float* __restrict__ b2,
                      float* __restrict__ out)
{
    extern __shared__ ull smem[];
    ull*    Zp = smem;                           // [LATENT][PSTRIDE]
    ull*    Hp = Zp + LATENT * PSTRIDE;          // [HIDDEN][PSTRIDE]
    ull*    Up = Hp + HIDDEN * PSTRIDE;          // [UDIM][PSTRIDE]
    float2* hp = (float2*)(Up + UDIM * PSTRIDE); // [NP]

    const int tid = threadIdx.x;
    const int l   = tid & 31;          // lane
    const int w   = tid >> 5;          // warp 0..7
    const int cg  = w & 1;             // column group (0/1)
    const int rg  = w >> 1;            // row group (0..3)
    const int rp0 = rg * 4;            // this warp's first row-pair
    const int row0 = blockIdx.x * TM;

    // ---- Load z (pair-packed, k-major). Consecutive tid -> consecutive k: coalesced.
    for (int idx = tid; idx < LATENT * NP; idx += THREADS) {
        int k  = idx & (LATENT - 1);
        int rp = idx >> 8;
        float a = zt[(row0 + 2 * rp    ) * LATENT + k];
        float b = zt[(row0 + 2 * rp + 1) * LATENT + k];
        Zp[k * PSTRIDE + rp] = pk2(a, b);
    }
    // ---- Load u (pair-packed, k-major)
    for (int idx = tid; idx < UDIM * NP; idx += THREADS) {
        int k  = idx & (UDIM - 1);
        int rp = idx >> 4;
        float a = ut[(row0 + 2 * rp    ) * UDIM + k];
        float b = ut[(row0 + 2 * rp + 1) * UDIM + k];
        Up[k * PSTRIDE + rp] = pk2(a, b);
    }
    // ---- Step size pairs h = dt/NSTEPS
    if (tid < NP) {
        hp[tid] = make_float2(dt[row0 + 2 * tid    ] * (1.0f / NSTEPS),
                              dt[row0 + 2 * tid + 1] * (1.0f / NSTEPS));
    }
    __syncthreads();

    const int c1 = cg * 256 + 4 * l;   // GEMM1: cols c1+{0..3} and c1+128+{0..3}
    const int c2 = cg * 128 + 4 * l;   // GEMM2: cols c2+{0..3}

    for (int s = 0; s < NSTEPS; s++) {
        // ================= GEMM1: H = tanh([z;u] @ W1 + b1) =================
        // Thread tile: 8 cols x 4 row-pairs (= 8 rows), 32 u64 accumulators.
        ull acc[2][4][4];
        #pragma unroll
        for (int q = 0; q < 2; q++)
            #pragma unroll
            for (int c = 0; c < 4; c++) {
                float bv = __ldg(b1 + c1 + q * 128 + c);
                ull bd = pk2(bv, bv);
                #pragma unroll
                for (int i = 0; i < 4; i++) acc[q][c][i] = bd;
            }

        // Full K loop over concatenated [z; u] (272 rows of W1).
        // Weight float4s are consumed immediately after packing to keep
        // peak live registers low (fits 128-reg budget at occupancy 2).
        #pragma unroll 2
        for (int kk = 0; kk < LATENT + UDIM; kk++) {
            ull xp[4];
            if (kk < LATENT) {
                #pragma unroll
                for (int i = 0; i < 4; i++) xp[i] = Zp[kk * PSTRIDE + rp0 + i]; // LDS.64 bcast
            } else {
                #pragma unroll
                for (int i = 0; i < 4; i++) xp[i] = Up[(kk - LATENT) * PSTRIDE + rp0 + i];
            }
            const float* wrow = W1 + kk * HIDDEN + c1;
            {
                const float4 wa = *(const float4*)(wrow);              // LDG.128
                ull w0 = pk2(wa.x, wa.x), w1v = pk2(wa.y, wa.y);
                ull w2v = pk2(wa.z, wa.z), w3 = pk2(wa.w, wa.w);
                #pragma unroll
                for (int i = 0; i < 4; i++) FFMA2(acc[0][0][i], w0,  xp[i]);
                #pragma unroll
                for (int i = 0; i < 4; i++) FFMA2(acc[0][1][i], w1v, xp[i]);
                #pragma unroll
                for (int i = 0; i < 4; i++) FFMA2(acc[0][2][i], w2v, xp[i]);
                #pragma unroll
                for (int i = 0; i < 4; i++) FFMA2(acc[0][3][i], w3,  xp[i]);
            }
            {
                const float4 wb = *(const float4*)(wrow + 128);        // LDG.128
                ull w0 = pk2(wb.x, wb.x), w1v = pk2(wb.y, wb.y);
                ull w2v = pk2(wb.z, wb.z), w3 = pk2(wb.w, wb.w);
                #pragma unroll
                for (int i = 0; i < 4; i++) FFMA2(acc[1][0][i], w0,  xp[i]);
                #pragma unroll
                for (int i = 0; i < 4; i++) FFMA2(acc[1][1][i], w1v, xp[i]);
                #pragma unroll
                for (int i = 0; i < 4; i++) FFMA2(acc[1][2][i], w2v, xp[i]);
                #pragma unroll
                for (int i = 0; i < 4; i++) FFMA2(acc[1][3][i], w3,  xp[i]);
            }
        }

        // tanh + store H pair-packed (k-major)
        #pragma unroll
        for (int q = 0; q < 2; q++)
            #pragma unroll
            for (int c = 0; c < 4; c++)
                #pragma unroll
                for (int i = 0; i < 4; i++) {
                    float2 v = upk(acc[q][c][i]);
                    v.x = tanhf(v.x);
                    v.y = tanhf(v.y);
                    Hp[(c1 + q * 128 + c) * PSTRIDE + rp0 + i] = pk2(v.x, v.y);
                }
        __syncthreads();

        // ================= GEMM2: F = H @ W2 + b2;  z += h*F =================
        // Thread tile: 4 cols x 4 row-pairs, 16 u64 accumulators.
        ull a2[4][4];
        #pragma unroll
        for (int c = 0; c < 4; c++) {
            float bv = __ldg(b2 + c2 + c);
            ull bd = pk2(bv, bv);
            #pragma unroll
            for (int i = 0; i < 4; i++) a2[c][i] = bd;
        }

        #pragma unroll 2
        for (int k = 0; k < HIDDEN; k++) {
            ull hd[4];
            #pragma unroll
            for (int i = 0; i < 4; i++) hd[i] = Hp[k * PSTRIDE + rp0 + i]; // LDS.64 bcast
            const float4 wv = *(const float4*)(W2 + k * LATENT + c2);       // LDG.128
            ull w0 = pk2(wv.x, wv.x), w1v = pk2(wv.y, wv.y);
            ull w2v = pk2(wv.z, wv.z), w3 = pk2(wv.w, wv.w);
            #pragma unroll
            for (int i = 0; i < 4; i++) FFMA2(a2[0][i], w0,  hd[i]);
            #pragma unroll
            for (int i = 0; i < 4; i++) FFMA2(a2[1][i], w1v, hd[i]);
            #pragma unroll
            for (int i = 0; i < 4; i++) FFMA2(a2[2][i], w2v, hd[i]);
            #pragma unroll
            for (int i = 0; i < 4; i++) FFMA2(a2[3][i], w3,  hd[i]);
        }

        // z += h * F  (each (col,rowpair) owned by exactly one thread)
        #pragma unroll
        for (int c = 0; c < 4; c++)
            #pragma unroll
            for (int i = 0; i < 4; i++) {
                const int zi = (c2 + c) * PSTRIDE + rp0 + i;
                float2 f = upk(a2[c][i]);
                float2 h = hp[rp0 + i];
                float2 z = upk(Zp[zi]);
                z.x += h.x * f.x;
                z.y += h.y * f.y;
                Zp[zi] = pk2(z.x, z.y);
            }
        __syncthreads();
    }

    // ---- Store z back, coalesced over k ----
    for (int idx = tid; idx < LATENT * NP * 2; idx += THREADS) {
        int k = idx & (LATENT - 1);
        int r = idx >> 8;                 // 0..31
        float2 v = upk(Zp[k * PSTRIDE + (r >> 1)]);
        out[(row0 + r) * LATENT + k] = (r & 1) ? v.y : v.x;
    }
}

extern "C" void kernel_launch(void* const* d_in, const int* in_sizes, int n_in,
                              void* d_out, int out_size)
{
    const float* zt = (const float*)d_in[0];
    const float* dt = (const float*)d_in[1];
    const float* ut = (const float*)d_in[2];
    const float* W1 = (const float*)d_in[3];
    const float* b1 = (const float*)d_in[4];
    const float* W2 = (const float*)d_in[5];
    const float* b2 = (const float*)d_in[6];
    float* out = (float*)d_out;

    const int B = 8192;
    const int grid = B / TM;   // 256 CTAs

    size_t smem_bytes = (size_t)(LATENT + HIDDEN + UDIM) * PSTRIDE * sizeof(ull)
                      + (size_t)NP * sizeof(float2);

    cudaFuncSetAttribute(node_euler_f32x2,
                         cudaFuncAttributeMaxDynamicSharedMemorySize,
                         (int)smem_bytes);

    node_euler_f32x2<<<grid, THREADS, smem_bytes>>>(zt, dt, ut, W1, b1, W2, b2, out);
}

// round 13
// speedup vs baseline: 3.4472x; 2.5006x over previous
#include <cuda_runtime.h>
#include <cstdint>

// Neural-ODE explicit Euler, 20 fused steps — mma.sync (HMMA) tf32 version.
// tcgen05 is ptxas-rejected in this harness (.target sm_103 without 'a'),
// so tensor work goes through classic m16n8k8 tf32 warp MMA.
//
// B=8192, LATENT=256, U=16, HIDDEN=512. TM=64 rows/CTA, grid=128, 256 thr.
// z state: fp32 in SMEM (exact across steps); MMA inputs tf32 (cvt.rna).
// Per step: 8 chunks of 64 H-cols:
//   stage W1 slice + W2 sub-slice (tf32), GEMM1 -> tanh.approx -> Hc(tf32),
//   GEMM2 accumulates into register D2 (warp owns 16x128, 64 regs).
// Then z += h * (D2 + b2); D2 re-armed with b2.

#define NSTEPS  20
#define TM      64
#define THREADS 256
#define LATENT  256
#define UDIM    16
#define KIN     272            // LATENT + UDIM
#define HIDDEN  512

#define ZSTR 276   // fp32 z|u rows [64][276]; (g*276+tig)%32 -> 32 distinct banks
#define WS1  72    // W1 chunk [272][72];  72%32==8  -> tig*8+g distinct
#define HS   68    // H  chunk [64][68];   68%32==4  -> g*4+tig distinct
#define WS2  264   // W2 sub   [32][264];  264%32==8 -> tig*8+g distinct

__device__ __forceinline__ uint32_t f2tf(float f) {
    uint32_t u; asm("cvt.rna.tf32.f32 %0, %1;" : "=r"(u) : "f"(f)); return u;
}
__device__ __forceinline__ float tanh_hw(float x) {
    float y; asm("tanh.approx.f32 %0, %1;" : "=f"(y) : "f"(x)); return y;
}
__device__ __forceinline__ void mma8(float* d, uint32_t a0, uint32_t a1,
                                     uint32_t a2, uint32_t a3,
                                     uint32_t b0, uint32_t b1) {
    asm("mma.sync.aligned.m16n8k8.row.col.f32.tf32.tf32.f32 "
        "{%0,%1,%2,%3}, {%4,%5,%6,%7}, {%8,%9}, {%0,%1,%2,%3};"
        : "+f"(d[0]), "+f"(d[1]), "+f"(d[2]), "+f"(d[3])
        : "r"(a0), "r"(a1), "r"(a2), "r"(a3), "r"(b0), "r"(b1));
}

__global__ __launch_bounds__(THREADS, 1)
void node_euler_hmma(const float* __restrict__ zt,
                     const float* __restrict__ dt,
                     const float* __restrict__ ut,
                     const float* __restrict__ W1,
                     const float* __restrict__ b1,
                     const float* __restrict__ W2,
                     const float* __restrict__ b2,
                     float* __restrict__ out)
{
    extern __shared__ uint32_t sm[];
    float*    Zs  = (float*)sm;                 // [64][ZSTR] fp32 (z cols 0..255, u 256..271)
    uint32_t* W1c = sm + TM * ZSTR;             // [272][WS1] tf32
    uint32_t* Hc  = W1c + KIN * WS1;            // [64][HS]   tf32
    uint32_t* W2c = Hc + TM * HS;               // [32][WS2]  tf32
    float*    b1s = (float*)(W2c + 32 * WS2);   // [512]
    float*    b2s = b1s + HIDDEN;               // [256]
    float*    hs  = b2s + LATENT;               // [64]

    const int tid  = threadIdx.x;
    const int w    = tid >> 5;
    const int lane = tid & 31;
    const int g    = lane >> 2;      // groupID 0..7
    const int tig  = lane & 3;       // thread-in-group 0..3
    const int wm   = w >> 1;         // m-tile 0..3
    const int wn   = w & 1;          // n-half 0..1
    const int m0   = wm * 16;
    const int row0 = blockIdx.x * TM;

    // ---- init: biases, step sizes, z|u state ----
    for (int i = tid; i < HIDDEN; i += THREADS) b1s[i] = b1[i];
    b2s[tid & 255] = b2[tid & 255];                    // 256 threads -> 256 vals
    if (tid < TM) hs[tid] = dt[row0 + tid] * (1.0f / NSTEPS);
    for (int j = 0; j < TM; j++)                       // z: coalesced rows
        Zs[j * ZSTR + tid] = zt[(row0 + j) * LATENT + tid];
    for (int i = tid; i < TM * UDIM; i += THREADS) {   // u
        int r = i >> 4, c = i & 15;
        Zs[r * ZSTR + LATENT + c] = ut[(row0 + r) * UDIM + c];
    }
    __syncthreads();

    // ---- persistent GEMM2 accumulators: warp tile 16 x 128 (nt=16 x m16n8) ----
    float d2[16][4];
    #pragma unroll
    for (int nt = 0; nt < 16; nt++) {
        int c0 = wn * 128 + nt * 8 + 2 * tig;
        d2[nt][0] = b2s[c0]; d2[nt][1] = b2s[c0 + 1];
        d2[nt][2] = b2s[c0]; d2[nt][3] = b2s[c0 + 1];
    }

    for (int s = 0; s < NSTEPS; s++) {
        for (int c = 0; c < 8; c++) {
            __syncthreads();   // prior chunk's GEMM2 / prior step's z-update done

            // ---- stage W1 slice [272][64c..64c+64) and W2 sub0 [64c..+32)[256] ----
            for (int j = 0; j < 68; j++) {
                int idx = tid + THREADS * j;
                int k = idx >> 6, n = idx & 63;
                W1c[k * WS1 + n] = f2tf(W1[k * HIDDEN + 64 * c + n]);
            }
            for (int j = 0; j < 32; j++)
                W2c[j * WS2 + tid] = f2tf(W2[(64 * c + j) * LATENT + tid]);
            __syncthreads();

            // ---- GEMM1: D1[16 x 32] = (z|u) @ W1 slice; warp cols wn*32.. ----
            float d1[4][4];
            #pragma unroll
            for (int tn = 0; tn < 4; tn++)
                d1[tn][0] = d1[tn][1] = d1[tn][2] = d1[tn][3] = 0.0f;

            #pragma unroll 2
            for (int kt = 0; kt < 34; kt++) {
                const int k0 = kt * 8;
                uint32_t a0 = f2tf(Zs[(m0 + g    ) * ZSTR + k0 + tig]);
                uint32_t a1 = f2tf(Zs[(m0 + g + 8) * ZSTR + k0 + tig]);
                uint32_t a2 = f2tf(Zs[(m0 + g    ) * ZSTR + k0 + tig + 4]);
                uint32_t a3 = f2tf(Zs[(m0 + g + 8) * ZSTR + k0 + tig + 4]);
                #pragma unroll
                for (int tn = 0; tn < 4; tn++) {
                    int nn = wn * 32 + tn * 8 + g;
                    uint32_t bb0 = W1c[(k0 + tig    ) * WS1 + nn];
                    uint32_t bb1 = W1c[(k0 + tig + 4) * WS1 + nn];
                    mma8(d1[tn], a0, a1, a2, a3, bb0, bb1);
                }
            }

            // ---- bias + tanh -> Hc (tf32) ----
            #pragma unroll
            for (int tn = 0; tn < 4; tn++) {
                int lc = wn * 32 + tn * 8 + 2 * tig;
                int gc = 64 * c + lc;
                float bv0 = b1s[gc], bv1 = b1s[gc + 1];
                uint2 v01 = make_uint2(f2tf(tanh_hw(d1[tn][0] + bv0)),
                                       f2tf(tanh_hw(d1[tn][1] + bv1)));
                uint2 v23 = make_uint2(f2tf(tanh_hw(d1[tn][2] + bv0)),
                                       f2tf(tanh_hw(d1[tn][3] + bv1)));
                *(uint2*)&Hc[(m0 + g    ) * HS + lc] = v01;
                *(uint2*)&Hc[(m0 + g + 8) * HS + lc] = v23;
            }
            __syncthreads();   // Hc ready (W2c sub0 already staged)

            // ---- GEMM2 sub0: D2 += Hc[:,0:32] @ W2 rows [64c..+32) ----
            #pragma unroll
            for (int kt2 = 0; kt2 < 4; kt2++) {
                const int k0 = kt2 * 8;
                uint32_t a0 = Hc[(m0 + g    ) * HS + k0 + tig];
                uint32_t a1 = Hc[(m0 + g + 8) * HS + k0 + tig];
                uint32_t a2 = Hc[(m0 + g    ) * HS + k0 + tig + 4];
                uint32_t a3 = Hc[(m0 + g + 8) * HS + k0 + tig + 4];
                #pragma unroll
                for (int nt = 0; nt < 16; nt++) {
                    int nn = wn * 128 + nt * 8 + g;
                    uint32_t bb0 = W2c[(k0 + tig    ) * WS2 + nn];
                    uint32_t bb1 = W2c[(k0 + tig + 4) * WS2 + nn];
                    mma8(d2[nt], a0, a1, a2, a3, bb0, bb1);
                }
            }
            __syncthreads();   // W2c consumed

            // ---- stage W2 sub1 [64c+32..+64)[256], GEMM2 sub1 (Hc cols 32..63) ----
            for (int j = 0; j < 32; j++)
                W2c[j * WS2 + tid] = f2tf(W2[(64 * c + 32 + j) * LATENT + tid]);
            __syncthreads();

            #pragma unroll
            for (int kt2 = 0; kt2 < 4; kt2++) {
                const int k0 = kt2 * 8;
                uint32_t a0 = Hc[(m0 + g    ) * HS + 32 + k0 + tig];
                uint32_t a1 = Hc[(m0 + g + 8) * HS + 32 + k0 + tig];
                uint32_t a2 = Hc[(m0 + g    ) * HS + 32 + k0 + tig + 4];
                uint32_t a3 = Hc[(m0 + g + 8) * HS + 32 + k0 + tig + 4];
                #pragma unroll
                for (int nt = 0; nt < 16; nt++) {
                    int nn = wn * 128 + nt * 8 + g;
                    uint32_t bb0 = W2c[(k0 + tig    ) * WS2 + nn];
                    uint32_t bb1 = W2c[(k0 + tig + 4) * WS2 + nn];
                    mma8(d2[nt], a0, a1, a2, a3, bb0, bb1);
                }
            }
        }

        // ---- z += h * (D2); re-arm D2 with b2 (each (row,col) single-owner) ----
        #pragma unroll
        for (int nt = 0; nt < 16; nt++) {
            int col = wn * 128 + nt * 8 + 2 * tig;
            int r0 = m0 + g, r1 = m0 + g + 8;
            float h0 = hs[r0], h1 = hs[r1];
            Zs[r0 * ZSTR + col    ] += h0 * d2[nt][0];
            Zs[r0 * ZSTR + col + 1] += h0 * d2[nt][1];
            Zs[r1 * ZSTR + col    ] += h1 * d2[nt][2];
            Zs[r1 * ZSTR + col + 1] += h1 * d2[nt][3];
            d2[nt][0] = b2s[col]; d2[nt][1] = b2s[col + 1];
            d2[nt][2] = b2s[col]; d2[nt][3] = b2s[col + 1];
        }
        __syncthreads();   // Zs updated before next step's GEMM1 reads
    }

    // ---- write result (coalesced) ----
    for (int j = 0; j < TM; j++)
        out[(row0 + j) * LATENT + tid] = Zs[j * ZSTR + tid];
}

extern "C" void kernel_launch(void* const* d_in, const int* in_sizes, int n_in,
                              void* d_out, int out_size)
{
    const float* zt = (const float*)d_in[0];
    const float* dt = (const float*)d_in[1];
    const float* ut = (const float*)d_in[2];
    const float* W1 = (const float*)d_in[3];
    const float* b1 = (const float*)d_in[4];
    const float* W2 = (const float*)d_in[5];
    const float* b2 = (const float*)d_in[6];
    float* out = (float*)d_out;

    const int grid = 8192 / TM;   // 128 CTAs

    size_t smem_bytes = (size_t)(TM * ZSTR + KIN * WS1 + TM * HS + 32 * WS2
                                 + HIDDEN + LATENT + TM) * 4;

    cudaFuncSetAttribute(node_euler_hmma,
                         cudaFuncAttributeMaxDynamicSharedMemorySize,
                         (int)smem_bytes);

    node_euler_hmma<<<grid, THREADS, smem_bytes>>>(zt, dt, ut, W1, b1, W2, b2, out);
}